// round 15
// baseline (speedup 1.0000x reference)
#include <cuda_runtime.h>
#include <cuda_fp16.h>
#include <math.h>
#include <stdint.h>

#define NUM_TOK 8192
#define HID     1024
#define INTERD  2816
#define NEXP    8
#define NROWS   (NUM_TOK * 2)
#define BM      128
#define M_MAX   (NROWS + NEXP * BM)      // 17408
#define NTILES  (M_MAX / BM)             // 136
#define QT      (NTILES / 4)             // 34
#define N1      (2 * INTERD)             // 5632

#define KSTEP   64
#define NCH1    (HID / KSTEP)            // 16
#define NCH2    (INTERD / KSTEP)         // 44

#define A_ROWB  144
#define A1TILE  (128 * A_ROWB)            // 18432
#define B1_ROWB 144
#define B1TILE  (64 * B1_ROWB)            // 9216
#define STG1    (A1TILE + 2 * B1TILE)     // 36864
#define S1      3

#define A2TILE  (128 * A_ROWB)
#define B2_ROWB 272
#define B2TILE  (64 * B2_ROWB)            // 17408
#define STG2    (A2TILE + B2TILE)         // 35840
#define S2      3

// ---------------- device scratch ----------------
__device__ int   g_perm_token[M_MAX];
__device__ float g_perm_w[M_MAX];
__device__ int   g_tile_expert[NTILES];
__device__ int   g_topk_i[NROWS];
__device__ float g_topk_w[NROWS];
__device__ int   g_inv[NROWS];

__device__ __half g_x16[(size_t)NUM_TOK * HID];
__device__ __half g_w1h[(size_t)NEXP * HID * N1];
__device__ __half g_w2h[(size_t)NEXP * INTERD * HID];
__device__ __half g_act[(size_t)M_MAX * INTERD];
__device__ float  g_y[(size_t)M_MAX * HID];

// ---------------- ptx helpers ----------------
__device__ __forceinline__ uint32_t s2u(const void* p) {
    uint32_t a;
    asm("{ .reg .u64 t; cvta.to.shared.u64 t, %1; cvt.u32.u64 %0, t; }" : "=r"(a) : "l"(p));
    return a;
}
__device__ __forceinline__ void ldsm4(uint32_t* r, uint32_t addr) {
    asm volatile("ldmatrix.sync.aligned.m8n8.x4.shared.b16 {%0,%1,%2,%3}, [%4];"
                 : "=r"(r[0]), "=r"(r[1]), "=r"(r[2]), "=r"(r[3]) : "r"(addr));
}
__device__ __forceinline__ void ldsm4t(uint32_t* r, uint32_t addr) {
    asm volatile("ldmatrix.sync.aligned.m8n8.x4.trans.shared.b16 {%0,%1,%2,%3}, [%4];"
                 : "=r"(r[0]), "=r"(r[1]), "=r"(r[2]), "=r"(r[3]) : "r"(addr));
}
__device__ __forceinline__ void mma16816(float* d, const uint32_t* a,
                                         uint32_t b0, uint32_t b1) {
    asm volatile(
        "mma.sync.aligned.m16n8k16.row.col.f32.f16.f16.f32 "
        "{%0,%1,%2,%3}, {%4,%5,%6,%7}, {%8,%9}, {%0,%1,%2,%3};"
        : "+f"(d[0]), "+f"(d[1]), "+f"(d[2]), "+f"(d[3])
        : "r"(a[0]), "r"(a[1]), "r"(a[2]), "r"(a[3]), "r"(b0), "r"(b1));
}
__device__ __forceinline__ void cp16(uint32_t dst, const void* src, int sz) {
    asm volatile("cp.async.cg.shared.global [%0], [%1], 16, %2;"
                 :: "r"(dst), "l"(src), "r"(sz));
}
#define CP_COMMIT() asm volatile("cp.async.commit_group;" ::: "memory")
#define CP_WAIT(n)  asm volatile("cp.async.wait_group %0;" :: "n"(n) : "memory")

// ---------------- small kernels ----------------
__global__ void convert_kernel(const float* __restrict__ src, __half* __restrict__ dst,
                               size_t n4) {
    size_t i = (size_t)blockIdx.x * blockDim.x + threadIdx.x;
    size_t stride = (size_t)gridDim.x * blockDim.x;
    for (size_t j = i; j < n4; j += stride) {
        float4 v = ((const float4*)src)[j];
        ((__half2*)dst)[2 * j]     = __floats2half2_rn(v.x, v.y);
        ((__half2*)dst)[2 * j + 1] = __floats2half2_rn(v.z, v.w);
    }
}

// gate + fused x fp32->fp16 convert; gw cached in smem (one warp per token)
__global__ void gate_kernel(const float* __restrict__ x, const float* __restrict__ gw) {
    __shared__ float s_gw[NEXP * HID];
    const int tid = threadIdx.x;
#pragma unroll
    for (int i = 0; i < NEXP * HID / 4 / 256; i++)
        ((float4*)s_gw)[i * 256 + tid] = ((const float4*)gw)[i * 256 + tid];
    __syncthreads();

    int warp = (blockIdx.x * blockDim.x + tid) >> 5;
    int lane = tid & 31;
    if (warp >= NUM_TOK) return;
    const float4* xr = (const float4*)(x + (size_t)warp * HID);
    __half2* xo = (__half2*)(g_x16 + (size_t)warp * HID);
    float acc[NEXP];
#pragma unroll
    for (int e = 0; e < NEXP; e++) acc[e] = 0.f;
#pragma unroll
    for (int it = 0; it < HID / 128; it++) {
        int h4 = it * 32 + lane;
        float4 xv = xr[h4];
        xo[2 * h4]     = __floats2half2_rn(xv.x, xv.y);
        xo[2 * h4 + 1] = __floats2half2_rn(xv.z, xv.w);
#pragma unroll
        for (int e = 0; e < NEXP; e++) {
            float4 gv = ((const float4*)(s_gw + e * HID))[h4];
            acc[e] += xv.x * gv.x + xv.y * gv.y + xv.z * gv.z + xv.w * gv.w;
        }
    }
#pragma unroll
    for (int e = 0; e < NEXP; e++)
#pragma unroll
        for (int o = 16; o > 0; o >>= 1)
            acc[e] += __shfl_xor_sync(0xffffffffu, acc[e], o);
    if (lane == 0) {
        int i1 = 0;
#pragma unroll
        for (int e = 1; e < NEXP; e++) if (acc[e] > acc[i1]) i1 = e;
        int i2 = (i1 == 0) ? 1 : 0;
#pragma unroll
        for (int e = 0; e < NEXP; e++) if (e != i1 && acc[e] > acc[i2]) i2 = e;
        float d  = expf(acc[i2] - acc[i1]);
        g_topk_i[warp * 2] = i1;     g_topk_i[warp * 2 + 1] = i2;
        g_topk_w[warp * 2] = 1.f / (1.f + d);
        g_topk_w[warp * 2 + 1] = d / (1.f + d);
    }
}

// fused histogram + scan + pad-fill + scatter (single block)
__global__ void __launch_bounds__(1024) scanscat_kernel() {
    __shared__ int s_cnt[NEXP], s_off[NEXP], s_pad[NEXP], s_fill[NEXP];
    const int tid = threadIdx.x;
    if (tid < NEXP) { s_cnt[tid] = 0; s_fill[tid] = 0; }
    __syncthreads();
    for (int i = tid; i < NROWS; i += 1024)
        atomicAdd(&s_cnt[g_topk_i[i]], 1);
    __syncthreads();
    if (tid == 0) {
        int off = 0;
        for (int e = 0; e < NEXP; e++) {
            s_off[e] = off;
            int padded = ((s_cnt[e] + BM - 1) / BM) * BM;
            s_pad[e] = padded;
            off += padded;
        }
    }
    __syncthreads();
    for (int r = tid; r < M_MAX; r += 1024) { g_perm_token[r] = -1; g_perm_w[r] = 0.f; }
    for (int t = tid; t < NTILES; t += 1024) {
        int row = t * BM, e = 0;
#pragma unroll
        for (int q = 0; q < NEXP; q++)
            if (row >= s_off[q] && row < s_off[q] + s_pad[q]) e = q;
        g_tile_expert[t] = e;
    }
    __syncthreads();
    for (int i = tid; i < NROWS; i += 1024) {
        int e = g_topk_i[i];
        int pos = s_off[e] + atomicAdd(&s_fill[e], 1);
        g_perm_token[pos] = i >> 1;
        g_perm_w[pos] = g_topk_w[i];
        g_inv[i] = pos;
    }
}

__global__ void combine_kernel(float* __restrict__ out) {
    int t = blockIdx.x;
    int h4 = threadIdx.x;
    size_t p0 = (size_t)g_inv[2 * t], p1 = (size_t)g_inv[2 * t + 1];
    float4 a = ((const float4*)(g_y + p0 * HID))[h4];
    float4 b = ((const float4*)(g_y + p1 * HID))[h4];
    ((float4*)(out + (size_t)t * HID))[h4] =
        make_float4(a.x + b.x, a.y + b.y, a.z + b.z, a.w + b.w);
}

// =================== GEMM1: 128M x 64N(gate)+64N(up), fused SiLU ============
__device__ __forceinline__ void g1_load(int c, int slot, uint32_t sb,
                                        const int* tok_s, int e, int nt, int tid) {
    const int k0 = c * KSTEP;
    const uint32_t base = sb + slot * STG1;
#pragma unroll
    for (int it = 0; it < 8; it++) {
        int u = it * 256 + tid;
        if (u < 1024) {
            int row = u >> 3, ch = u & 7;
            int tok = tok_s[row];
            int sz = (tok < 0) ? 0 : 16;
            if (tok < 0) tok = 0;
            cp16(base + row * A_ROWB + ch * 16,
                 g_x16 + (size_t)tok * HID + k0 + ch * 8, sz);
        } else {
            int v = u - 1024;
            int mat = v >> 9, w = v & 511;
            int row = w >> 3, ch = w & 7;
            const __half* src = g_w1h + ((size_t)e * HID + k0 + row) * N1
                                + mat * INTERD + nt * 64 + ch * 8;
            cp16(base + A1TILE + mat * B1TILE + row * B1_ROWB + ch * 16, src, 16);
        }
    }
    CP_COMMIT();
}

__global__ void __launch_bounds__(256, 2) gemm1_kernel(int mt_base) {
    extern __shared__ __align__(128) char dsm[];
    __shared__ int tok_s[BM];

    const int nt = blockIdx.x, mt = mt_base + blockIdx.y;
    const int e = g_tile_expert[mt];
    const int tid = threadIdx.x, wid = tid >> 5, lane = tid & 31;
    const int wm = wid >> 1, wn = wid & 1;
    const uint32_t sb = s2u(dsm);

    if (tid < BM) tok_s[tid] = g_perm_token[mt * BM + tid];
    __syncthreads();

    float accg[2][4][4], accu[2][4][4];
#pragma unroll
    for (int i = 0; i < 2; i++)
#pragma unroll
        for (int j = 0; j < 4; j++)
#pragma unroll
            for (int q = 0; q < 4; q++) { accg[i][j][q] = 0.f; accu[i][j][q] = 0.f; }

    g1_load(0, 0, sb, tok_s, e, nt, tid);
    g1_load(1, 1, sb, tok_s, e, nt, tid);

    const int lrow = lane & 15;
    const int lhi  = (lane >> 4) * 16;

    for (int c = 0; c < NCH1; c++) {
        CP_WAIT(1);
        __syncthreads();
        if (c + 2 < NCH1) g1_load(c + 2, (c + 2) % S1, sb, tok_s, e, nt, tid);
        else CP_COMMIT();

        uint32_t stA  = sb + (c % S1) * STG1;
        uint32_t stBg = stA + A1TILE;
        uint32_t stBu = stBg + B1TILE;
#pragma unroll
        for (int kk = 0; kk < 4; kk++) {
            uint32_t a[2][4];
#pragma unroll
            for (int i = 0; i < 2; i++)
                ldsm4(a[i], stA + (wm * 32 + i * 16 + lrow) * A_ROWB + kk * 32 + lhi);
            uint32_t bg[2][4], bu[2][4];
#pragma unroll
            for (int g = 0; g < 2; g++) {
                uint32_t roff = (kk * 16 + lrow) * B1_ROWB + (wn * 32 + g * 16) * 2 + lhi;
                ldsm4t(bg[g], stBg + roff);
                ldsm4t(bu[g], stBu + roff);
            }
#pragma unroll
            for (int i = 0; i < 2; i++) {
                mma16816(accg[i][0], a[i], bg[0][0], bg[0][1]);
                mma16816(accg[i][1], a[i], bg[0][2], bg[0][3]);
                mma16816(accg[i][2], a[i], bg[1][0], bg[1][1]);
                mma16816(accg[i][3], a[i], bg[1][2], bg[1][3]);
                mma16816(accu[i][0], a[i], bu[0][0], bu[0][1]);
                mma16816(accu[i][1], a[i], bu[0][2], bu[0][3]);
                mma16816(accu[i][2], a[i], bu[1][0], bu[1][1]);
                mma16816(accu[i][3], a[i], bu[1][2], bu[1][3]);
            }
        }
    }

    const int qr = lane >> 2, qc = lane & 3;
#pragma unroll
    for (int i = 0; i < 2; i++) {
        int r0 = mt * BM + wm * 32 + i * 16 + qr;
#pragma unroll
        for (int j = 0; j < 4; j++) {
            int col = nt * 64 + wn * 32 + j * 8 + qc * 2;
            {
                float g0 = accg[i][j][0], g1 = accg[i][j][1];
                float u0 = accu[i][j][0], u1 = accu[i][j][1];
                float a0 = g0 * u0 / (1.f + __expf(-g0));
                float a1 = g1 * u1 / (1.f + __expf(-g1));
                *(__half2*)(g_act + (size_t)r0 * INTERD + col) = __floats2half2_rn(a0, a1);
            }
            {
                float g0 = accg[i][j][2], g1 = accg[i][j][3];
                float u0 = accu[i][j][2], u1 = accu[i][j][3];
                float a0 = g0 * u0 / (1.f + __expf(-g0));
                float a1 = g1 * u1 / (1.f + __expf(-g1));
                *(__half2*)(g_act + (size_t)(r0 + 8) * INTERD + col) = __floats2half2_rn(a0, a1);
            }
        }
    }
}

// =================== GEMM2: 128M x 128N, weighted plain-store ===============
__device__ __forceinline__ void g2_load(int c, int slot, uint32_t sb,
                                        int mt, int e, int nt, int tid) {
    const int k0 = c * KSTEP;
    const uint32_t base = sb + slot * STG2;
#pragma unroll
    for (int it = 0; it < 8; it++) {
        int u = it * 256 + tid;
        if (u < 1024) {
            int row = u >> 3, ch = u & 7;
            cp16(base + row * A_ROWB + ch * 16,
                 g_act + (size_t)(mt * BM + row) * INTERD + k0 + ch * 8, 16);
        } else {
            int v = u - 1024;
            int row = v >> 4, ch = v & 15;
            const __half* src = g_w2h + ((size_t)e * INTERD + k0 + row) * HID
                                + nt * 128 + ch * 8;
            cp16(base + A2TILE + row * B2_ROWB + ch * 16, src, 16);
        }
    }
    CP_COMMIT();
}

__global__ void __launch_bounds__(256, 2) gemm2_kernel(int mt_base) {
    extern __shared__ __align__(128) char dsm[];
    __shared__ float w_s[BM];

    const int nt = blockIdx.x, mt = mt_base + blockIdx.y;
    const int e = g_tile_expert[mt];
    const int tid = threadIdx.x, wid = tid >> 5, lane = tid & 31;
    const int wm = wid >> 1, wn = wid & 1;
    const uint32_t sb = s2u(dsm);

    if (tid < BM) w_s[tid] = g_perm_w[mt * BM + tid];
    __syncthreads();

    float acc[2][8][4];
#pragma unroll
    for (int i = 0; i < 2; i++)
#pragma unroll
        for (int j = 0; j < 8; j++)
#pragma unroll
            for (int q = 0; q < 4; q++) acc[i][j][q] = 0.f;

    g2_load(0, 0, sb, mt, e, nt, tid);
    g2_load(1, 1, sb, mt, e, nt, tid);

    const int lrow = lane & 15;
    const int lhi  = (lane >> 4) * 16;

    for (int c = 0; c < NCH2; c++) {
        CP_WAIT(1);
        __syncthreads();
        if (c + 2 < NCH2) g2_load(c + 2, (c + 2) % S2, sb, mt, e, nt, tid);
        else CP_COMMIT();

        uint32_t stA = sb + (c % S2) * STG2;
        uint32_t stB = stA + A2TILE;
#pragma unroll
        for (int kk = 0; kk < 4; kk++) {
            uint32_t a[2][4];
#pragma unroll
            for (int i = 0; i < 2; i++)
                ldsm4(a[i], stA + (wm * 32 + i * 16 + lrow) * A_ROWB + kk * 32 + lhi);
            uint32_t bq[4][4];
#pragma unroll
            for (int g = 0; g < 4; g++)
                ldsm4t(bq[g], stB + (kk * 16 + lrow) * B2_ROWB
                              + (wn * 64 + g * 16) * 2 + lhi);
#pragma unroll
            for (int i = 0; i < 2; i++)
#pragma unroll
                for (int j = 0; j < 8; j++)
                    mma16816(acc[i][j], a[i], bq[j >> 1][(j & 1) * 2],
                             bq[j >> 1][(j & 1) * 2 + 1]);
        }
    }

    const int qr = lane >> 2, qc = lane & 3;
#pragma unroll
    for (int i = 0; i < 2; i++) {
        int rl = wm * 32 + i * 16 + qr;
        size_t r0 = (size_t)(mt * BM + rl);
        float w0 = w_s[rl], w1v = w_s[rl + 8];
#pragma unroll
        for (int j = 0; j < 8; j++) {
            int col = nt * 128 + wn * 64 + j * 8 + qc * 2;
            *(float2*)(g_y + r0 * HID + col) =
                make_float2(w0 * acc[i][j][0], w0 * acc[i][j][1]);
            *(float2*)(g_y + (r0 + 8) * HID + col) =
                make_float2(w1v * acc[i][j][2], w1v * acc[i][j][3]);
        }
    }
}

// ---------------- launch: quarter-interleaved, capture-legal order ----------
extern "C" void kernel_launch(void* const* d_in, const int* in_sizes, int n_in,
                              void* d_out, int out_size) {
    const float* x  = (const float*)d_in[0];
    const float* gw = (const float*)d_in[1];
    const float* w1 = (const float*)d_in[2];
    const float* w2 = (const float*)d_in[3];
    float* out = (float*)d_out;

    static __half* p_w1h = nullptr;
    static __half* p_w2h = nullptr;
    static cudaStream_t sA, sB;
    static cudaEvent_t eRoot, eScan, eW1, eW2, eGA, eGB, eQ[4];
    if (!p_w1h) {
        cudaGetSymbolAddress((void**)&p_w1h, g_w1h);
        cudaGetSymbolAddress((void**)&p_w2h, g_w2h);
        cudaFuncSetAttribute(gemm1_kernel, cudaFuncAttributeMaxDynamicSharedMemorySize, S1 * STG1);
        cudaFuncSetAttribute(gemm2_kernel, cudaFuncAttributeMaxDynamicSharedMemorySize, S2 * STG2);
        cudaFuncSetAttribute(gemm1_kernel, cudaFuncAttributePreferredSharedMemoryCarveout, 100);
        cudaFuncSetAttribute(gemm2_kernel, cudaFuncAttributePreferredSharedMemoryCarveout, 100);
        cudaStreamCreateWithFlags(&sA, cudaStreamNonBlocking);
        cudaStreamCreateWithFlags(&sB, cudaStreamNonBlocking);
        cudaEventCreateWithFlags(&eRoot, cudaEventDisableTiming);
        cudaEventCreateWithFlags(&eScan, cudaEventDisableTiming);
        cudaEventCreateWithFlags(&eW1,   cudaEventDisableTiming);
        cudaEventCreateWithFlags(&eW2,   cudaEventDisableTiming);
        cudaEventCreateWithFlags(&eGA,   cudaEventDisableTiming);
        cudaEventCreateWithFlags(&eGB,   cudaEventDisableTiming);
        for (int i = 0; i < 4; i++)
            cudaEventCreateWithFlags(&eQ[i], cudaEventDisableTiming);
    }

    cudaEventRecord(eRoot, 0);
    cudaStreamWaitEvent(sA, eRoot, 0);
    cudaStreamWaitEvent(sB, eRoot, 0);

    // converts run concurrently up front
    convert_kernel<<<4096, 256, 0, sA>>>(w1, p_w1h, (size_t)NEXP * HID * N1 / 4);
    cudaEventRecord(eW1, sA);
    convert_kernel<<<4096, 256, 0, sB>>>(w2, p_w2h, (size_t)NEXP * INTERD * HID / 4);
    cudaEventRecord(eW2, sB);

    // routing on main stream (overlaps converts)
    gate_kernel<<<NUM_TOK / 8, 256>>>(x, gw);
    scanscat_kernel<<<1, 1024>>>();
    cudaEventRecord(eScan, 0);

    // ---- phase 1: all g1 quarters, alternating streams; record each ----
    cudaStreamWaitEvent(sA, eScan, 0);                 // sA already has eW1 in-order
    cudaStreamWaitEvent(sB, eScan, 0);
    cudaStreamWaitEvent(sB, eW1, 0);

    gemm1_kernel<<<dim3(INTERD / 64, QT), 256, S1 * STG1, sA>>>(0 * QT);
    cudaEventRecord(eQ[0], sA);
    gemm1_kernel<<<dim3(INTERD / 64, QT), 256, S1 * STG1, sB>>>(1 * QT);
    cudaEventRecord(eQ[1], sB);
    gemm1_kernel<<<dim3(INTERD / 64, QT), 256, S1 * STG1, sA>>>(2 * QT);
    cudaEventRecord(eQ[2], sA);
    gemm1_kernel<<<dim3(INTERD / 64, QT), 256, S1 * STG1, sB>>>(3 * QT);
    cudaEventRecord(eQ[3], sB);

    // ---- phase 2: g2 quarters, each waiting only on its own g1 quarter ----
    cudaStreamWaitEvent(sA, eW2, 0);
    cudaStreamWaitEvent(sA, eQ[1], 0);                 // recorded above: legal
    gemm2_kernel<<<dim3(HID / 128, QT), 256, S2 * STG2, sA>>>(1 * QT);
    cudaStreamWaitEvent(sB, eQ[0], 0);                 // sB already has eW2 in-order
    gemm2_kernel<<<dim3(HID / 128, QT), 256, S2 * STG2, sB>>>(0 * QT);
    cudaStreamWaitEvent(sA, eQ[3], 0);
    gemm2_kernel<<<dim3(HID / 128, QT), 256, S2 * STG2, sA>>>(3 * QT);
    cudaStreamWaitEvent(sB, eQ[2], 0);
    gemm2_kernel<<<dim3(HID / 128, QT), 256, S2 * STG2, sB>>>(2 * QT);

    cudaEventRecord(eGA, sA);
    cudaEventRecord(eGB, sB);

    // join + combine
    cudaStreamWaitEvent(0, eGA, 0);
    cudaStreamWaitEvent(0, eGB, 0);
    combine_kernel<<<NUM_TOK, 256>>>(out);
}

// round 16
// speedup vs baseline: 1.0847x; 1.0847x over previous
#include <cuda_runtime.h>
#include <cuda_fp16.h>
#include <math.h>
#include <stdint.h>

#define NUM_TOK 8192
#define HID     1024
#define INTERD  2816
#define NEXP    8
#define NROWS   (NUM_TOK * 2)
#define BM      128
#define M_MAX   (NROWS + NEXP * BM)      // 17408
#define NTILES  (M_MAX / BM)             // 136
#define HTILES  (NTILES / 2)             // 68
#define N1      (2 * INTERD)             // 5632

#define KSTEP   64
#define NCH1    (HID / KSTEP)            // 16
#define NCH2    (INTERD / KSTEP)         // 44

#define A_ROWB  144
#define A1TILE  (128 * A_ROWB)            // 18432
#define B1_ROWB 144
#define B1TILE  (64 * B1_ROWB)            // 9216
#define STG1    (A1TILE + 2 * B1TILE)     // 36864
#define S1      3

#define A2TILE  (128 * A_ROWB)
#define B2_ROWB 272
#define B2TILE  (64 * B2_ROWB)            // 17408
#define STG2    (A2TILE + B2TILE)         // 35840
#define S2      3

// ---------------- device scratch ----------------
__device__ int   g_perm_token[M_MAX];
__device__ float g_perm_w[M_MAX];
__device__ int   g_tile_expert[NTILES];
__device__ int   g_topk_i[NROWS];
__device__ float g_topk_w[NROWS];
__device__ int   g_inv[NROWS];

__device__ __half g_x16[(size_t)NUM_TOK * HID];
__device__ __half g_w1h[(size_t)NEXP * HID * N1];
__device__ __half g_w2h[(size_t)NEXP * INTERD * HID];
__device__ __half g_act[(size_t)M_MAX * INTERD];
__device__ float  g_y[(size_t)M_MAX * HID];

// ---------------- ptx helpers ----------------
__device__ __forceinline__ uint32_t s2u(const void* p) {
    uint32_t a;
    asm("{ .reg .u64 t; cvta.to.shared.u64 t, %1; cvt.u32.u64 %0, t; }" : "=r"(a) : "l"(p));
    return a;
}
__device__ __forceinline__ void ldsm4(uint32_t* r, uint32_t addr) {
    asm volatile("ldmatrix.sync.aligned.m8n8.x4.shared.b16 {%0,%1,%2,%3}, [%4];"
                 : "=r"(r[0]), "=r"(r[1]), "=r"(r[2]), "=r"(r[3]) : "r"(addr));
}
__device__ __forceinline__ void ldsm4t(uint32_t* r, uint32_t addr) {
    asm volatile("ldmatrix.sync.aligned.m8n8.x4.trans.shared.b16 {%0,%1,%2,%3}, [%4];"
                 : "=r"(r[0]), "=r"(r[1]), "=r"(r[2]), "=r"(r[3]) : "r"(addr));
}
__device__ __forceinline__ void mma16816(float* d, const uint32_t* a,
                                         uint32_t b0, uint32_t b1) {
    asm volatile(
        "mma.sync.aligned.m16n8k16.row.col.f32.f16.f16.f32 "
        "{%0,%1,%2,%3}, {%4,%5,%6,%7}, {%8,%9}, {%0,%1,%2,%3};"
        : "+f"(d[0]), "+f"(d[1]), "+f"(d[2]), "+f"(d[3])
        : "r"(a[0]), "r"(a[1]), "r"(a[2]), "r"(a[3]), "r"(b0), "r"(b1));
}
__device__ __forceinline__ void cp16(uint32_t dst, const void* src, int sz) {
    asm volatile("cp.async.cg.shared.global [%0], [%1], 16, %2;"
                 :: "r"(dst), "l"(src), "r"(sz));
}
#define CP_COMMIT() asm volatile("cp.async.commit_group;" ::: "memory")
#define CP_WAIT(n)  asm volatile("cp.async.wait_group %0;" :: "n"(n) : "memory")

// ---------------- small kernels ----------------
__global__ void convert_kernel(const float* __restrict__ src, __half* __restrict__ dst,
                               size_t n4) {
    size_t i = (size_t)blockIdx.x * blockDim.x + threadIdx.x;
    size_t stride = (size_t)gridDim.x * blockDim.x;
    for (size_t j = i; j < n4; j += stride) {
        float4 v = ((const float4*)src)[j];
        ((__half2*)dst)[2 * j]     = __floats2half2_rn(v.x, v.y);
        ((__half2*)dst)[2 * j + 1] = __floats2half2_rn(v.z, v.w);
    }
}

// gate + fused x fp32->fp16 convert; gw cached in smem (one warp per token)
__global__ void gate_kernel(const float* __restrict__ x, const float* __restrict__ gw) {
    __shared__ float s_gw[NEXP * HID];
    const int tid = threadIdx.x;
#pragma unroll
    for (int i = 0; i < NEXP * HID / 4 / 256; i++)
        ((float4*)s_gw)[i * 256 + tid] = ((const float4*)gw)[i * 256 + tid];
    __syncthreads();

    int warp = (blockIdx.x * blockDim.x + tid) >> 5;
    int lane = tid & 31;
    if (warp >= NUM_TOK) return;
    const float4* xr = (const float4*)(x + (size_t)warp * HID);
    __half2* xo = (__half2*)(g_x16 + (size_t)warp * HID);
    float acc[NEXP];
#pragma unroll
    for (int e = 0; e < NEXP; e++) acc[e] = 0.f;
#pragma unroll
    for (int it = 0; it < HID / 128; it++) {
        int h4 = it * 32 + lane;
        float4 xv = xr[h4];
        xo[2 * h4]     = __floats2half2_rn(xv.x, xv.y);
        xo[2 * h4 + 1] = __floats2half2_rn(xv.z, xv.w);
#pragma unroll
        for (int e = 0; e < NEXP; e++) {
            float4 gv = ((const float4*)(s_gw + e * HID))[h4];
            acc[e] += xv.x * gv.x + xv.y * gv.y + xv.z * gv.z + xv.w * gv.w;
        }
    }
#pragma unroll
    for (int e = 0; e < NEXP; e++)
#pragma unroll
        for (int o = 16; o > 0; o >>= 1)
            acc[e] += __shfl_xor_sync(0xffffffffu, acc[e], o);
    if (lane == 0) {
        int i1 = 0;
#pragma unroll
        for (int e = 1; e < NEXP; e++) if (acc[e] > acc[i1]) i1 = e;
        int i2 = (i1 == 0) ? 1 : 0;
#pragma unroll
        for (int e = 0; e < NEXP; e++) if (e != i1 && acc[e] > acc[i2]) i2 = e;
        float d  = expf(acc[i2] - acc[i1]);
        g_topk_i[warp * 2] = i1;     g_topk_i[warp * 2 + 1] = i2;
        g_topk_w[warp * 2] = 1.f / (1.f + d);
        g_topk_w[warp * 2 + 1] = d / (1.f + d);
    }
}

// fused histogram + scan + pad-fill + scatter (single block)
__global__ void __launch_bounds__(1024) scanscat_kernel() {
    __shared__ int s_cnt[NEXP], s_off[NEXP], s_pad[NEXP], s_fill[NEXP];
    const int tid = threadIdx.x;
    if (tid < NEXP) { s_cnt[tid] = 0; s_fill[tid] = 0; }
    __syncthreads();
    for (int i = tid; i < NROWS; i += 1024)
        atomicAdd(&s_cnt[g_topk_i[i]], 1);
    __syncthreads();
    if (tid == 0) {
        int off = 0;
        for (int e = 0; e < NEXP; e++) {
            s_off[e] = off;
            int padded = ((s_cnt[e] + BM - 1) / BM) * BM;
            s_pad[e] = padded;
            off += padded;
        }
    }
    __syncthreads();
    for (int r = tid; r < M_MAX; r += 1024) { g_perm_token[r] = -1; g_perm_w[r] = 0.f; }
    for (int t = tid; t < NTILES; t += 1024) {
        int row = t * BM, e = 0;
#pragma unroll
        for (int q = 0; q < NEXP; q++)
            if (row >= s_off[q] && row < s_off[q] + s_pad[q]) e = q;
        g_tile_expert[t] = e;
    }
    __syncthreads();
    for (int i = tid; i < NROWS; i += 1024) {
        int e = g_topk_i[i];
        int pos = s_off[e] + atomicAdd(&s_fill[e], 1);
        g_perm_token[pos] = i >> 1;
        g_perm_w[pos] = g_topk_w[i];
        g_inv[i] = pos;
    }
}

__global__ void combine_kernel(float* __restrict__ out) {
    int t = blockIdx.x;
    int h4 = threadIdx.x;
    size_t p0 = (size_t)g_inv[2 * t], p1 = (size_t)g_inv[2 * t + 1];
    float4 a = ((const float4*)(g_y + p0 * HID))[h4];
    float4 b = ((const float4*)(g_y + p1 * HID))[h4];
    ((float4*)(out + (size_t)t * HID))[h4] =
        make_float4(a.x + b.x, a.y + b.y, a.z + b.z, a.w + b.w);
}

// =================== GEMM1: 128M x 64N(gate)+64N(up), fused SiLU ============
__device__ __forceinline__ void g1_load(int c, int slot, uint32_t sb,
                                        const int* tok_s, int e, int nt, int tid) {
    const int k0 = c * KSTEP;
    const uint32_t base = sb + slot * STG1;
#pragma unroll
    for (int it = 0; it < 8; it++) {
        int u = it * 256 + tid;
        if (u < 1024) {
            int row = u >> 3, ch = u & 7;
            int tok = tok_s[row];
            int sz = (tok < 0) ? 0 : 16;
            if (tok < 0) tok = 0;
            cp16(base + row * A_ROWB + ch * 16,
                 g_x16 + (size_t)tok * HID + k0 + ch * 8, sz);
        } else {
            int v = u - 1024;
            int mat = v >> 9, w = v & 511;
            int row = w >> 3, ch = w & 7;
            const __half* src = g_w1h + ((size_t)e * HID + k0 + row) * N1
                                + mat * INTERD + nt * 64 + ch * 8;
            cp16(base + A1TILE + mat * B1TILE + row * B1_ROWB + ch * 16, src, 16);
        }
    }
    CP_COMMIT();
}

__global__ void __launch_bounds__(256, 2) gemm1_kernel(int mt_base) {
    extern __shared__ __align__(128) char dsm[];
    __shared__ int tok_s[BM];

    const int nt = blockIdx.x, mt = mt_base + blockIdx.y;
    const int e = g_tile_expert[mt];
    const int tid = threadIdx.x, wid = tid >> 5, lane = tid & 31;
    const int wm = wid >> 1, wn = wid & 1;
    const uint32_t sb = s2u(dsm);

    if (tid < BM) tok_s[tid] = g_perm_token[mt * BM + tid];
    __syncthreads();

    float accg[2][4][4], accu[2][4][4];
#pragma unroll
    for (int i = 0; i < 2; i++)
#pragma unroll
        for (int j = 0; j < 4; j++)
#pragma unroll
            for (int q = 0; q < 4; q++) { accg[i][j][q] = 0.f; accu[i][j][q] = 0.f; }

    g1_load(0, 0, sb, tok_s, e, nt, tid);
    g1_load(1, 1, sb, tok_s, e, nt, tid);

    const int lrow = lane & 15;
    const int lhi  = (lane >> 4) * 16;

    for (int c = 0; c < NCH1; c++) {
        CP_WAIT(1);
        __syncthreads();

        uint32_t stA  = sb + (c % S1) * STG1;
        uint32_t stBg = stA + A1TILE;
        uint32_t stBu = stBg + B1TILE;
#pragma unroll
        for (int kk = 0; kk < 4; kk++) {
            uint32_t a[2][4];
#pragma unroll
            for (int i = 0; i < 2; i++)
                ldsm4(a[i], stA + (wm * 32 + i * 16 + lrow) * A_ROWB + kk * 32 + lhi);
            uint32_t bg[2][4], bu[2][4];
#pragma unroll
            for (int g = 0; g < 2; g++) {
                uint32_t roff = (kk * 16 + lrow) * B1_ROWB + (wn * 32 + g * 16) * 2 + lhi;
                ldsm4t(bg[g], stBg + roff);
                ldsm4t(bu[g], stBu + roff);
            }
#pragma unroll
            for (int i = 0; i < 2; i++) {
                mma16816(accg[i][0], a[i], bg[0][0], bg[0][1]);
                mma16816(accg[i][1], a[i], bg[0][2], bg[0][3]);
                mma16816(accg[i][2], a[i], bg[1][0], bg[1][1]);
                mma16816(accg[i][3], a[i], bg[1][2], bg[1][3]);
                mma16816(accu[i][0], a[i], bu[0][0], bu[0][1]);
                mma16816(accu[i][1], a[i], bu[0][2], bu[0][3]);
                mma16816(accu[i][2], a[i], bu[1][0], bu[1][1]);
                mma16816(accu[i][3], a[i], bu[1][2], bu[1][3]);
            }
            // spread the cp.async burst into the mma-rich middle of the chunk
            if (kk == 1) {
                if (c + 2 < NCH1) g1_load(c + 2, (c + 2) % S1, sb, tok_s, e, nt, tid);
                else CP_COMMIT();
            }
        }
    }

    const int qr = lane >> 2, qc = lane & 3;
#pragma unroll
    for (int i = 0; i < 2; i++) {
        int r0 = mt * BM + wm * 32 + i * 16 + qr;
#pragma unroll
        for (int j = 0; j < 4; j++) {
            int col = nt * 64 + wn * 32 + j * 8 + qc * 2;
            {
                float g0 = accg[i][j][0], g1 = accg[i][j][1];
                float u0 = accu[i][j][0], u1 = accu[i][j][1];
                float a0 = g0 * u0 / (1.f + __expf(-g0));
                float a1 = g1 * u1 / (1.f + __expf(-g1));
                *(__half2*)(g_act + (size_t)r0 * INTERD + col) = __floats2half2_rn(a0, a1);
            }
            {
                float g0 = accg[i][j][2], g1 = accg[i][j][3];
                float u0 = accu[i][j][2], u1 = accu[i][j][3];
                float a0 = g0 * u0 / (1.f + __expf(-g0));
                float a1 = g1 * u1 / (1.f + __expf(-g1));
                *(__half2*)(g_act + (size_t)(r0 + 8) * INTERD + col) = __floats2half2_rn(a0, a1);
            }
        }
    }
}

// =================== GEMM2: 128M x 128N, weighted plain-store ===============
__device__ __forceinline__ void g2_load(int c, int slot, uint32_t sb,
                                        int mt, int e, int nt, int tid) {
    const int k0 = c * KSTEP;
    const uint32_t base = sb + slot * STG2;
#pragma unroll
    for (int it = 0; it < 8; it++) {
        int u = it * 256 + tid;
        if (u < 1024) {
            int row = u >> 3, ch = u & 7;
            cp16(base + row * A_ROWB + ch * 16,
                 g_act + (size_t)(mt * BM + row) * INTERD + k0 + ch * 8, 16);
        } else {
            int v = u - 1024;
            int row = v >> 4, ch = v & 15;
            const __half* src = g_w2h + ((size_t)e * INTERD + k0 + row) * HID
                                + nt * 128 + ch * 8;
            cp16(base + A2TILE + row * B2_ROWB + ch * 16, src, 16);
        }
    }
    CP_COMMIT();
}

__global__ void __launch_bounds__(256, 2) gemm2_kernel(int mt_base) {
    extern __shared__ __align__(128) char dsm[];
    __shared__ float w_s[BM];

    const int nt = blockIdx.x, mt = mt_base + blockIdx.y;
    const int e = g_tile_expert[mt];
    const int tid = threadIdx.x, wid = tid >> 5, lane = tid & 31;
    const int wm = wid >> 1, wn = wid & 1;
    const uint32_t sb = s2u(dsm);

    if (tid < BM) w_s[tid] = g_perm_w[mt * BM + tid];
    __syncthreads();

    float acc[2][8][4];
#pragma unroll
    for (int i = 0; i < 2; i++)
#pragma unroll
        for (int j = 0; j < 8; j++)
#pragma unroll
            for (int q = 0; q < 4; q++) acc[i][j][q] = 0.f;

    g2_load(0, 0, sb, mt, e, nt, tid);
    g2_load(1, 1, sb, mt, e, nt, tid);

    const int lrow = lane & 15;
    const int lhi  = (lane >> 4) * 16;

    for (int c = 0; c < NCH2; c++) {
        CP_WAIT(1);
        __syncthreads();

        uint32_t stA = sb + (c % S2) * STG2;
        uint32_t stB = stA + A2TILE;
#pragma unroll
        for (int kk = 0; kk < 4; kk++) {
            uint32_t a[2][4];
#pragma unroll
            for (int i = 0; i < 2; i++)
                ldsm4(a[i], stA + (wm * 32 + i * 16 + lrow) * A_ROWB + kk * 32 + lhi);
            uint32_t bq[4][4];
#pragma unroll
            for (int g = 0; g < 4; g++)
                ldsm4t(bq[g], stB + (kk * 16 + lrow) * B2_ROWB
                              + (wn * 64 + g * 16) * 2 + lhi);
#pragma unroll
            for (int i = 0; i < 2; i++)
#pragma unroll
                for (int j = 0; j < 8; j++)
                    mma16816(acc[i][j], a[i], bq[j >> 1][(j & 1) * 2],
                             bq[j >> 1][(j & 1) * 2 + 1]);
            if (kk == 1) {
                if (c + 2 < NCH2) g2_load(c + 2, (c + 2) % S2, sb, mt, e, nt, tid);
                else CP_COMMIT();
            }
        }
    }

    const int qr = lane >> 2, qc = lane & 3;
#pragma unroll
    for (int i = 0; i < 2; i++) {
        int rl = wm * 32 + i * 16 + qr;
        size_t r0 = (size_t)(mt * BM + rl);
        float w0 = w_s[rl], w1v = w_s[rl + 8];
#pragma unroll
        for (int j = 0; j < 8; j++) {
            int col = nt * 128 + wn * 64 + j * 8 + qc * 2;
            *(float2*)(g_y + r0 * HID + col) =
                make_float2(w0 * acc[i][j][0], w0 * acc[i][j][1]);
            *(float2*)(g_y + (r0 + 8) * HID + col) =
                make_float2(w1v * acc[i][j][2], w1v * acc[i][j][3]);
        }
    }
}

// ---------------- launch: 2-chain pipelined schedule (R12) ----------------
extern "C" void kernel_launch(void* const* d_in, const int* in_sizes, int n_in,
                              void* d_out, int out_size) {
    const float* x  = (const float*)d_in[0];
    const float* gw = (const float*)d_in[1];
    const float* w1 = (const float*)d_in[2];
    const float* w2 = (const float*)d_in[3];
    float* out = (float*)d_out;

    static __half* p_w1h = nullptr;
    static __half* p_w2h = nullptr;
    static cudaStream_t sA, sB;
    static cudaEvent_t eRoot, eScan, eW1, eW2, eGA, eGB;
    if (!p_w1h) {
        cudaGetSymbolAddress((void**)&p_w1h, g_w1h);
        cudaGetSymbolAddress((void**)&p_w2h, g_w2h);
        cudaFuncSetAttribute(gemm1_kernel, cudaFuncAttributeMaxDynamicSharedMemorySize, S1 * STG1);
        cudaFuncSetAttribute(gemm2_kernel, cudaFuncAttributeMaxDynamicSharedMemorySize, S2 * STG2);
        cudaFuncSetAttribute(gemm1_kernel, cudaFuncAttributePreferredSharedMemoryCarveout, 100);
        cudaFuncSetAttribute(gemm2_kernel, cudaFuncAttributePreferredSharedMemoryCarveout, 100);
        cudaStreamCreateWithFlags(&sA, cudaStreamNonBlocking);
        cudaStreamCreateWithFlags(&sB, cudaStreamNonBlocking);
        cudaEventCreateWithFlags(&eRoot, cudaEventDisableTiming);
        cudaEventCreateWithFlags(&eScan, cudaEventDisableTiming);
        cudaEventCreateWithFlags(&eW1,   cudaEventDisableTiming);
        cudaEventCreateWithFlags(&eW2,   cudaEventDisableTiming);
        cudaEventCreateWithFlags(&eGA,   cudaEventDisableTiming);
        cudaEventCreateWithFlags(&eGB,   cudaEventDisableTiming);
    }

    cudaEventRecord(eRoot, 0);
    cudaStreamWaitEvent(sA, eRoot, 0);
    cudaStreamWaitEvent(sB, eRoot, 0);

    // converts run concurrently up front
    convert_kernel<<<4096, 256, 0, sA>>>(w1, p_w1h, (size_t)NEXP * HID * N1 / 4);
    cudaEventRecord(eW1, sA);
    convert_kernel<<<4096, 256, 0, sB>>>(w2, p_w2h, (size_t)NEXP * INTERD * HID / 4);
    cudaEventRecord(eW2, sB);

    // routing on main stream (overlaps converts)
    gate_kernel<<<NUM_TOK / 8, 256>>>(x, gw);
    scanscat_kernel<<<1, 1024>>>();
    cudaEventRecord(eScan, 0);

    // chain A on sA: gemm1 lower half -> gemm2 lower half
    cudaStreamWaitEvent(sA, eScan, 0);
    gemm1_kernel<<<dim3(INTERD / 64, HTILES), 256, S1 * STG1, sA>>>(0);
    cudaStreamWaitEvent(sA, eW2, 0);
    gemm2_kernel<<<dim3(HID / 128, HTILES), 256, S2 * STG2, sA>>>(0);
    cudaEventRecord(eGA, sA);

    // chain B on sB: gemm1 upper half -> gemm2 upper half
    cudaStreamWaitEvent(sB, eScan, 0);
    cudaStreamWaitEvent(sB, eW1, 0);
    gemm1_kernel<<<dim3(INTERD / 64, HTILES), 256, S1 * STG1, sB>>>(HTILES);
    gemm2_kernel<<<dim3(HID / 128, HTILES), 256, S2 * STG2, sB>>>(HTILES);
    cudaEventRecord(eGB, sB);

    // join + combine
    cudaStreamWaitEvent(0, eGA, 0);
    cudaStreamWaitEvent(0, eGB, 0);
    combine_kernel<<<NUM_TOK, 256>>>(out);
}

// round 17
// speedup vs baseline: 1.1087x; 1.0222x over previous
#include <cuda_runtime.h>
#include <cuda_fp16.h>
#include <math.h>
#include <stdint.h>

#define NUM_TOK 8192
#define HID     1024
#define INTERD  2816
#define NEXP    8
#define NROWS   (NUM_TOK * 2)
#define BM      128
#define M_MAX   (NROWS + NEXP * BM)      // 17408
#define NTILES  (M_MAX / BM)             // 136
#define HTILES  (NTILES / 2)             // 68
#define N1      (2 * INTERD)             // 5632

#define KSTEP   64
#define NCH1    (HID / KSTEP)            // 16
#define NCH2    (INTERD / KSTEP)         // 44

#define A_ROWB  144
#define A1TILE  (128 * A_ROWB)            // 18432
#define B1_ROWB 144
#define B1TILE  (64 * B1_ROWB)            // 9216
#define STG1    (A1TILE + 2 * B1TILE)     // 36864
#define S1      3

#define A2TILE  (128 * A_ROWB)
#define B2_ROWB 272
#define B2TILE  (64 * B2_ROWB)            // 17408
#define STG2    (A2TILE + B2TILE)         // 35840
#define S2      3

// ---------------- device scratch ----------------
__device__ int   g_perm_token[M_MAX];
__device__ float g_perm_w[M_MAX];
__device__ int   g_tile_expert[NTILES];
__device__ int   g_topk_i[NROWS];
__device__ float g_topk_w[NROWS];
__device__ int   g_inv[NROWS];

__device__ __half g_x16[(size_t)NUM_TOK * HID];
__device__ __half g_w1h[(size_t)NEXP * HID * N1];
__device__ __half g_w2h[(size_t)NEXP * INTERD * HID];
__device__ __half g_act[(size_t)M_MAX * INTERD];
__device__ float  g_y[(size_t)M_MAX * HID];

// ---------------- ptx helpers ----------------
__device__ __forceinline__ uint32_t s2u(const void* p) {
    uint32_t a;
    asm("{ .reg .u64 t; cvta.to.shared.u64 t, %1; cvt.u32.u64 %0, t; }" : "=r"(a) : "l"(p));
    return a;
}
__device__ __forceinline__ void ldsm4(uint32_t* r, uint32_t addr) {
    asm volatile("ldmatrix.sync.aligned.m8n8.x4.shared.b16 {%0,%1,%2,%3}, [%4];"
                 : "=r"(r[0]), "=r"(r[1]), "=r"(r[2]), "=r"(r[3]) : "r"(addr));
}
__device__ __forceinline__ void ldsm4t(uint32_t* r, uint32_t addr) {
    asm volatile("ldmatrix.sync.aligned.m8n8.x4.trans.shared.b16 {%0,%1,%2,%3}, [%4];"
                 : "=r"(r[0]), "=r"(r[1]), "=r"(r[2]), "=r"(r[3]) : "r"(addr));
}
__device__ __forceinline__ void mma16816(float* d, const uint32_t* a,
                                         uint32_t b0, uint32_t b1) {
    asm volatile(
        "mma.sync.aligned.m16n8k16.row.col.f32.f16.f16.f32 "
        "{%0,%1,%2,%3}, {%4,%5,%6,%7}, {%8,%9}, {%0,%1,%2,%3};"
        : "+f"(d[0]), "+f"(d[1]), "+f"(d[2]), "+f"(d[3])
        : "r"(a[0]), "r"(a[1]), "r"(a[2]), "r"(a[3]), "r"(b0), "r"(b1));
}
__device__ __forceinline__ void cp16(uint32_t dst, const void* src, int sz) {
    asm volatile("cp.async.cg.shared.global [%0], [%1], 16, %2;"
                 :: "r"(dst), "l"(src), "r"(sz));
}
#define CP_COMMIT() asm volatile("cp.async.commit_group;" ::: "memory")
#define CP_WAIT(n)  asm volatile("cp.async.wait_group %0;" :: "n"(n) : "memory")

// ---------------- small kernels ----------------
__global__ void convert_kernel(const float* __restrict__ src, __half* __restrict__ dst,
                               size_t n4) {
    size_t i = (size_t)blockIdx.x * blockDim.x + threadIdx.x;
    size_t stride = (size_t)gridDim.x * blockDim.x;
    for (size_t j = i; j < n4; j += stride) {
        float4 v = ((const float4*)src)[j];
        ((__half2*)dst)[2 * j]     = __floats2half2_rn(v.x, v.y);
        ((__half2*)dst)[2 * j + 1] = __floats2half2_rn(v.z, v.w);
    }
}

// gate + fused x fp32->fp16 convert; gw cached in smem (one warp per token)
__global__ void gate_kernel(const float* __restrict__ x, const float* __restrict__ gw) {
    __shared__ float s_gw[NEXP * HID];
    const int tid = threadIdx.x;
#pragma unroll
    for (int i = 0; i < NEXP * HID / 4 / 256; i++)
        ((float4*)s_gw)[i * 256 + tid] = ((const float4*)gw)[i * 256 + tid];
    __syncthreads();

    int warp = (blockIdx.x * blockDim.x + tid) >> 5;
    int lane = tid & 31;
    if (warp >= NUM_TOK) return;
    const float4* xr = (const float4*)(x + (size_t)warp * HID);
    __half2* xo = (__half2*)(g_x16 + (size_t)warp * HID);
    float acc[NEXP];
#pragma unroll
    for (int e = 0; e < NEXP; e++) acc[e] = 0.f;
#pragma unroll
    for (int it = 0; it < HID / 128; it++) {
        int h4 = it * 32 + lane;
        float4 xv = xr[h4];
        xo[2 * h4]     = __floats2half2_rn(xv.x, xv.y);
        xo[2 * h4 + 1] = __floats2half2_rn(xv.z, xv.w);
#pragma unroll
        for (int e = 0; e < NEXP; e++) {
            float4 gv = ((const float4*)(s_gw + e * HID))[h4];
            acc[e] += xv.x * gv.x + xv.y * gv.y + xv.z * gv.z + xv.w * gv.w;
        }
    }
#pragma unroll
    for (int e = 0; e < NEXP; e++)
#pragma unroll
        for (int o = 16; o > 0; o >>= 1)
            acc[e] += __shfl_xor_sync(0xffffffffu, acc[e], o);
    if (lane == 0) {
        int i1 = 0;
#pragma unroll
        for (int e = 1; e < NEXP; e++) if (acc[e] > acc[i1]) i1 = e;
        int i2 = (i1 == 0) ? 1 : 0;
#pragma unroll
        for (int e = 0; e < NEXP; e++) if (e != i1 && acc[e] > acc[i2]) i2 = e;
        float d  = expf(acc[i2] - acc[i1]);
        g_topk_i[warp * 2] = i1;     g_topk_i[warp * 2 + 1] = i2;
        g_topk_w[warp * 2] = 1.f / (1.f + d);
        g_topk_w[warp * 2 + 1] = d / (1.f + d);
    }
}

// fused histogram + scan + pad-fill + scatter (single block)
__global__ void __launch_bounds__(1024) scanscat_kernel() {
    __shared__ int s_cnt[NEXP], s_off[NEXP], s_pad[NEXP], s_fill[NEXP];
    const int tid = threadIdx.x;
    if (tid < NEXP) { s_cnt[tid] = 0; s_fill[tid] = 0; }
    __syncthreads();
    for (int i = tid; i < NROWS; i += 1024)
        atomicAdd(&s_cnt[g_topk_i[i]], 1);
    __syncthreads();
    if (tid == 0) {
        int off = 0;
        for (int e = 0; e < NEXP; e++) {
            s_off[e] = off;
            int padded = ((s_cnt[e] + BM - 1) / BM) * BM;
            s_pad[e] = padded;
            off += padded;
        }
    }
    __syncthreads();
    for (int r = tid; r < M_MAX; r += 1024) { g_perm_token[r] = -1; g_perm_w[r] = 0.f; }
    for (int t = tid; t < NTILES; t += 1024) {
        int row = t * BM, e = 0;
#pragma unroll
        for (int q = 0; q < NEXP; q++)
            if (row >= s_off[q] && row < s_off[q] + s_pad[q]) e = q;
        g_tile_expert[t] = e;
    }
    __syncthreads();
    for (int i = tid; i < NROWS; i += 1024) {
        int e = g_topk_i[i];
        int pos = s_off[e] + atomicAdd(&s_fill[e], 1);
        g_perm_token[pos] = i >> 1;
        g_perm_w[pos] = g_topk_w[i];
        g_inv[i] = pos;
    }
}

__global__ void combine_kernel(float* __restrict__ out) {
    int t = blockIdx.x;
    int h4 = threadIdx.x;
    size_t p0 = (size_t)g_inv[2 * t], p1 = (size_t)g_inv[2 * t + 1];
    float4 a = ((const float4*)(g_y + p0 * HID))[h4];
    float4 b = ((const float4*)(g_y + p1 * HID))[h4];
    ((float4*)(out + (size_t)t * HID))[h4] =
        make_float4(a.x + b.x, a.y + b.y, a.z + b.z, a.w + b.w);
}

// =================== GEMM1: 128M x 64N(gate)+64N(up), fused SiLU ============
// half = 0: iterations 0-3, half = 1: iterations 4-7 (commit only after half 1)
__device__ __forceinline__ void g1_load_half(int c, int slot, uint32_t sb,
                                             const int* tok_s, int e, int nt,
                                             int tid, int half) {
    const int k0 = c * KSTEP;
    const uint32_t base = sb + slot * STG1;
#pragma unroll
    for (int it = half * 4; it < half * 4 + 4; it++) {
        int u = it * 256 + tid;
        if (u < 1024) {
            int row = u >> 3, ch = u & 7;
            int tok = tok_s[row];
            int sz = (tok < 0) ? 0 : 16;
            if (tok < 0) tok = 0;
            cp16(base + row * A_ROWB + ch * 16,
                 g_x16 + (size_t)tok * HID + k0 + ch * 8, sz);
        } else {
            int v = u - 1024;
            int mat = v >> 9, w = v & 511;
            int row = w >> 3, ch = w & 7;
            const __half* src = g_w1h + ((size_t)e * HID + k0 + row) * N1
                                + mat * INTERD + nt * 64 + ch * 8;
            cp16(base + A1TILE + mat * B1TILE + row * B1_ROWB + ch * 16, src, 16);
        }
    }
    if (half == 1) CP_COMMIT();
}

__global__ void __launch_bounds__(256, 2) gemm1_kernel(int mt_base) {
    extern __shared__ __align__(128) char dsm[];
    __shared__ int tok_s[BM];

    const int nt = blockIdx.x, mt = mt_base + blockIdx.y;
    const int e = g_tile_expert[mt];
    const int tid = threadIdx.x, wid = tid >> 5, lane = tid & 31;
    const int wm = wid >> 1, wn = wid & 1;
    const uint32_t sb = s2u(dsm);

    if (tid < BM) tok_s[tid] = g_perm_token[mt * BM + tid];
    __syncthreads();

    float accg[2][4][4], accu[2][4][4];
#pragma unroll
    for (int i = 0; i < 2; i++)
#pragma unroll
        for (int j = 0; j < 4; j++)
#pragma unroll
            for (int q = 0; q < 4; q++) { accg[i][j][q] = 0.f; accu[i][j][q] = 0.f; }

    g1_load_half(0, 0, sb, tok_s, e, nt, tid, 0);
    g1_load_half(0, 0, sb, tok_s, e, nt, tid, 1);
    g1_load_half(1, 1, sb, tok_s, e, nt, tid, 0);
    g1_load_half(1, 1, sb, tok_s, e, nt, tid, 1);

    const int lrow = lane & 15;
    const int lhi  = (lane >> 4) * 16;

    for (int c = 0; c < NCH1; c++) {
        CP_WAIT(1);
        __syncthreads();

        uint32_t stA  = sb + (c % S1) * STG1;
        uint32_t stBg = stA + A1TILE;
        uint32_t stBu = stBg + B1TILE;
        const bool more = (c + 2 < NCH1);
#pragma unroll
        for (int kk = 0; kk < 4; kk++) {
            uint32_t a[2][4];
#pragma unroll
            for (int i = 0; i < 2; i++)
                ldsm4(a[i], stA + (wm * 32 + i * 16 + lrow) * A_ROWB + kk * 32 + lhi);
            uint32_t bg[2][4], bu[2][4];
#pragma unroll
            for (int g = 0; g < 2; g++) {
                uint32_t roff = (kk * 16 + lrow) * B1_ROWB + (wn * 32 + g * 16) * 2 + lhi;
                ldsm4t(bg[g], stBg + roff);
                ldsm4t(bu[g], stBu + roff);
            }
#pragma unroll
            for (int i = 0; i < 2; i++) {
                mma16816(accg[i][0], a[i], bg[0][0], bg[0][1]);
                mma16816(accg[i][1], a[i], bg[0][2], bg[0][3]);
                mma16816(accg[i][2], a[i], bg[1][0], bg[1][1]);
                mma16816(accg[i][3], a[i], bg[1][2], bg[1][3]);
                mma16816(accu[i][0], a[i], bu[0][0], bu[0][1]);
                mma16816(accu[i][1], a[i], bu[0][2], bu[0][3]);
                mma16816(accu[i][2], a[i], bu[1][0], bu[1][1]);
                mma16816(accu[i][3], a[i], bu[1][2], bu[1][3]);
            }
            // spread next-chunk cp.async across two mma-rich injection points
            if (kk == 1) {
                if (more) g1_load_half(c + 2, (c + 2) % S1, sb, tok_s, e, nt, tid, 0);
            } else if (kk == 2) {
                if (more) g1_load_half(c + 2, (c + 2) % S1, sb, tok_s, e, nt, tid, 1);
                else CP_COMMIT();
            }
        }
    }

    const int qr = lane >> 2, qc = lane & 3;
#pragma unroll
    for (int i = 0; i < 2; i++) {
        int r0 = mt * BM + wm * 32 + i * 16 + qr;
#pragma unroll
        for (int j = 0; j < 4; j++) {
            int col = nt * 64 + wn * 32 + j * 8 + qc * 2;
            {
                float g0 = accg[i][j][0], g1 = accg[i][j][1];
                float u0 = accu[i][j][0], u1 = accu[i][j][1];
                float a0 = g0 * u0 / (1.f + __expf(-g0));
                float a1 = g1 * u1 / (1.f + __expf(-g1));
                *(__half2*)(g_act + (size_t)r0 * INTERD + col) = __floats2half2_rn(a0, a1);
            }
            {
                float g0 = accg[i][j][2], g1 = accg[i][j][3];
                float u0 = accu[i][j][2], u1 = accu[i][j][3];
                float a0 = g0 * u0 / (1.f + __expf(-g0));
                float a1 = g1 * u1 / (1.f + __expf(-g1));
                *(__half2*)(g_act + (size_t)(r0 + 8) * INTERD + col) = __floats2half2_rn(a0, a1);
            }
        }
    }
}

// =================== GEMM2: 128M x 128N, weighted plain-store ===============
__device__ __forceinline__ void g2_load_half(int c, int slot, uint32_t sb,
                                             int mt, int e, int nt, int tid, int half) {
    const int k0 = c * KSTEP;
    const uint32_t base = sb + slot * STG2;
#pragma unroll
    for (int it = half * 4; it < half * 4 + 4; it++) {
        int u = it * 256 + tid;
        if (u < 1024) {
            int row = u >> 3, ch = u & 7;
            cp16(base + row * A_ROWB + ch * 16,
                 g_act + (size_t)(mt * BM + row) * INTERD + k0 + ch * 8, 16);
        } else {
            int v = u - 1024;
            int row = v >> 4, ch = v & 15;
            const __half* src = g_w2h + ((size_t)e * INTERD + k0 + row) * HID
                                + nt * 128 + ch * 8;
            cp16(base + A2TILE + row * B2_ROWB + ch * 16, src, 16);
        }
    }
    if (half == 1) CP_COMMIT();
}

__global__ void __launch_bounds__(256, 2) gemm2_kernel(int mt_base) {
    extern __shared__ __align__(128) char dsm[];
    __shared__ float w_s[BM];

    const int nt = blockIdx.x, mt = mt_base + blockIdx.y;
    const int e = g_tile_expert[mt];
    const int tid = threadIdx.x, wid = tid >> 5, lane = tid & 31;
    const int wm = wid >> 1, wn = wid & 1;
    const uint32_t sb = s2u(dsm);

    if (tid < BM) w_s[tid] = g_perm_w[mt * BM + tid];
    __syncthreads();

    float acc[2][8][4];
#pragma unroll
    for (int i = 0; i < 2; i++)
#pragma unroll
        for (int j = 0; j < 8; j++)
#pragma unroll
            for (int q = 0; q < 4; q++) acc[i][j][q] = 0.f;

    g2_load_half(0, 0, sb, mt, e, nt, tid, 0);
    g2_load_half(0, 0, sb, mt, e, nt, tid, 1);
    g2_load_half(1, 1, sb, mt, e, nt, tid, 0);
    g2_load_half(1, 1, sb, mt, e, nt, tid, 1);

    const int lrow = lane & 15;
    const int lhi  = (lane >> 4) * 16;

    for (int c = 0; c < NCH2; c++) {
        CP_WAIT(1);
        __syncthreads();

        uint32_t stA = sb + (c % S2) * STG2;
        uint32_t stB = stA + A2TILE;
        const bool more = (c + 2 < NCH2);
#pragma unroll
        for (int kk = 0; kk < 4; kk++) {
            uint32_t a[2][4];
#pragma unroll
            for (int i = 0; i < 2; i++)
                ldsm4(a[i], stA + (wm * 32 + i * 16 + lrow) * A_ROWB + kk * 32 + lhi);
            uint32_t bq[4][4];
#pragma unroll
            for (int g = 0; g < 4; g++)
                ldsm4t(bq[g], stB + (kk * 16 + lrow) * B2_ROWB
                              + (wn * 64 + g * 16) * 2 + lhi);
#pragma unroll
            for (int i = 0; i < 2; i++)
#pragma unroll
                for (int j = 0; j < 8; j++)
                    mma16816(acc[i][j], a[i], bq[j >> 1][(j & 1) * 2],
                             bq[j >> 1][(j & 1) * 2 + 1]);
            if (kk == 1) {
                if (more) g2_load_half(c + 2, (c + 2) % S2, sb, mt, e, nt, tid, 0);
            } else if (kk == 2) {
                if (more) g2_load_half(c + 2, (c + 2) % S2, sb, mt, e, nt, tid, 1);
                else CP_COMMIT();
            }
        }
    }

    const int qr = lane >> 2, qc = lane & 3;
#pragma unroll
    for (int i = 0; i < 2; i++) {
        int rl = wm * 32 + i * 16 + qr;
        size_t r0 = (size_t)(mt * BM + rl);
        float w0 = w_s[rl], w1v = w_s[rl + 8];
#pragma unroll
        for (int j = 0; j < 8; j++) {
            int col = nt * 128 + wn * 64 + j * 8 + qc * 2;
            *(float2*)(g_y + r0 * HID + col) =
                make_float2(w0 * acc[i][j][0], w0 * acc[i][j][1]);
            *(float2*)(g_y + (r0 + 8) * HID + col) =
                make_float2(w1v * acc[i][j][2], w1v * acc[i][j][3]);
        }
    }
}

// ---------------- launch: 2-chain pipelined schedule (R12) ----------------
extern "C" void kernel_launch(void* const* d_in, const int* in_sizes, int n_in,
                              void* d_out, int out_size) {
    const float* x  = (const float*)d_in[0];
    const float* gw = (const float*)d_in[1];
    const float* w1 = (const float*)d_in[2];
    const float* w2 = (const float*)d_in[3];
    float* out = (float*)d_out;

    static __half* p_w1h = nullptr;
    static __half* p_w2h = nullptr;
    static cudaStream_t sA, sB;
    static cudaEvent_t eRoot, eScan, eW1, eW2, eGA, eGB;
    if (!p_w1h) {
        cudaGetSymbolAddress((void**)&p_w1h, g_w1h);
        cudaGetSymbolAddress((void**)&p_w2h, g_w2h);
        cudaFuncSetAttribute(gemm1_kernel, cudaFuncAttributeMaxDynamicSharedMemorySize, S1 * STG1);
        cudaFuncSetAttribute(gemm2_kernel, cudaFuncAttributeMaxDynamicSharedMemorySize, S2 * STG2);
        cudaFuncSetAttribute(gemm1_kernel, cudaFuncAttributePreferredSharedMemoryCarveout, 100);
        cudaFuncSetAttribute(gemm2_kernel, cudaFuncAttributePreferredSharedMemoryCarveout, 100);
        cudaStreamCreateWithFlags(&sA, cudaStreamNonBlocking);
        cudaStreamCreateWithFlags(&sB, cudaStreamNonBlocking);
        cudaEventCreateWithFlags(&eRoot, cudaEventDisableTiming);
        cudaEventCreateWithFlags(&eScan, cudaEventDisableTiming);
        cudaEventCreateWithFlags(&eW1,   cudaEventDisableTiming);
        cudaEventCreateWithFlags(&eW2,   cudaEventDisableTiming);
        cudaEventCreateWithFlags(&eGA,   cudaEventDisableTiming);
        cudaEventCreateWithFlags(&eGB,   cudaEventDisableTiming);
    }

    cudaEventRecord(eRoot, 0);
    cudaStreamWaitEvent(sA, eRoot, 0);
    cudaStreamWaitEvent(sB, eRoot, 0);

    // converts run concurrently up front
    convert_kernel<<<4096, 256, 0, sA>>>(w1, p_w1h, (size_t)NEXP * HID * N1 / 4);
    cudaEventRecord(eW1, sA);
    convert_kernel<<<4096, 256, 0, sB>>>(w2, p_w2h, (size_t)NEXP * INTERD * HID / 4);
    cudaEventRecord(eW2, sB);

    // routing on main stream (overlaps converts)
    gate_kernel<<<NUM_TOK / 8, 256>>>(x, gw);
    scanscat_kernel<<<1, 1024>>>();
    cudaEventRecord(eScan, 0);

    // chain A on sA: gemm1 lower half -> gemm2 lower half
    cudaStreamWaitEvent(sA, eScan, 0);
    gemm1_kernel<<<dim3(INTERD / 64, HTILES), 256, S1 * STG1, sA>>>(0);
    cudaStreamWaitEvent(sA, eW2, 0);
    gemm2_kernel<<<dim3(HID / 128, HTILES), 256, S2 * STG2, sA>>>(0);
    cudaEventRecord(eGA, sA);

    // chain B on sB: gemm1 upper half -> gemm2 upper half
    cudaStreamWaitEvent(sB, eScan, 0);
    cudaStreamWaitEvent(sB, eW1, 0);
    gemm1_kernel<<<dim3(INTERD / 64, HTILES), 256, S1 * STG1, sB>>>(HTILES);
    gemm2_kernel<<<dim3(HID / 128, HTILES), 256, S2 * STG2, sB>>>(HTILES);
    cudaEventRecord(eGB, sB);

    // join + combine
    cudaStreamWaitEvent(0, eGA, 0);
    cudaStreamWaitEvent(0, eGB, 0);
    combine_kernel<<<NUM_TOK, 256>>>(out);
}